// round 3
// baseline (speedup 1.0000x reference)
#include <cuda_runtime.h>
#include <cstdint>
#include <math_constants.h>

// Problem constants
#define BATCH      64
#define SEQ        2048
#define H_DIM      1024
#define NSPLIT     16
#define ROWS_PER_ITEM (SEQ / NSPLIT)             // 128
#define TOTAL_ITEMS   (BATCH * NSPLIT)           // 1024
#define STAGE_ROWS 16
#define NSTAGES    (ROWS_PER_ITEM / STAGE_ROWS)  // 8 stages per item
#define NBUF       3
#define STAGE_BYTES (STAGE_ROWS * H_DIM * 4)     // 65536
#define SMEM_BUF_BYTES (NBUF * STAGE_BYTES)      // 196608
#define MBAR_OFF   SMEM_BUF_BYTES
#define META_OFF   (SMEM_BUF_BYTES + 64)
#define COMB_OFF   (SMEM_BUF_BYTES + 512)
#define SMEM_TOTAL (COMB_OFF + 32768)            // 229888 <= 232448 cap
#define GRID       152

// Cross-CTA scratch (allocation-free: __device__ globals)
__device__ float g_num[BATCH * NSPLIT * H_DIM];  // per-split exp-weighted numerator
__device__ float g_ml[BATCH * NSPLIT * 2];       // per-split (M, L)
__device__ int   g_cnt[BATCH];                   // per-batch arrival counters (self-reset)
__device__ int   g_work;                         // work-stealing counter (self-reset)
__device__ int   g_done;                         // CTA finish counter (self-reset)

// ---------------- PTX helpers ----------------
__device__ __forceinline__ uint32_t smem_u32(const void* p) {
    uint32_t a;
    asm("{ .reg .u64 t; cvta.to.shared.u64 t, %1; cvt.u32.u64 %0, t; }"
        : "=r"(a) : "l"(p));
    return a;
}

#define MBARRIER_INIT(addr, count) \
    asm volatile("mbarrier.init.shared.b64 [%0], %1;" \
                 :: "r"((uint32_t)(addr)), "r"((uint32_t)(count)) : "memory")

#define MBARRIER_EXPECT_TX(addr, bytes) \
    asm volatile("mbarrier.arrive.expect_tx.shared.b64 _, [%0], %1;" \
                 :: "r"((uint32_t)(addr)), "r"((uint32_t)(bytes)) : "memory")

#define MBARRIER_WAIT_PARITY(mbar_smem_addr, phase_parity) do { \
    uint32_t _mbar = (uint32_t)(mbar_smem_addr); \
    uint32_t _parity = (uint32_t)(phase_parity); \
    uint32_t _done; \
    asm volatile( \
        "{\n\t" \
        ".reg .pred p;\n\t" \
        "mbarrier.try_wait.parity.acquire.cta.shared::cta.b64 p, [%1], %2;\n\t" \
        "selp.b32 %0, 1, 0, p;\n\t" \
        "}" \
        : "=r"(_done) : "r"(_mbar), "r"(_parity) : "memory"); \
    if (!_done) { \
        asm volatile( \
            "{\n\t" \
            ".reg .pred P1;\n\t" \
            "WAIT_LOOP_%=:\n\t" \
            "mbarrier.try_wait.parity.acquire.cta.shared::cta.b64 P1, [%0], %1, 0x989680;\n\t" \
            "@P1 bra.uni WAIT_DONE_%=;\n\t" \
            "bra.uni WAIT_LOOP_%=;\n\t" \
            "WAIT_DONE_%=:\n\t" \
            "}" \
            :: "r"(_mbar), "r"(_parity) : "memory"); \
    } \
} while (0)

#define BULK_G2S(dst_smem, src_gmem, nbytes, mbar) \
    asm volatile("cp.async.bulk.shared::cluster.global.mbarrier::complete_tx::bytes " \
                 "[%0], [%1], %2, [%3];" \
                 :: "r"((uint32_t)(dst_smem)), "l"(src_gmem), \
                    "r"((uint32_t)(nbytes)), "r"((uint32_t)(mbar)) : "memory")

__device__ __forceinline__ const char* item_src(const float* enc, int item) {
    const int b = item >> 4;          // item / NSPLIT
    const int sp = item & (NSPLIT - 1);
    return (const char*)(enc + ((size_t)b * SEQ + (size_t)sp * ROWS_PER_ITEM) * H_DIM);
}

// ---------------- Persistent fused split-KV attention ----------------
// 152 persistent CTAs, 256 threads. Each CTA runs a continuous 3-deep TMA
// stage pipeline; work items (128 seq rows) are claimed by atomicAdd exactly
// when the pipeline lookahead crosses an item boundary, so the stream never
// drains. Warp w handles rows {w*2, w*2+1} of each 16-row stage; lane l owns
// columns {l*4 + i*128 + j}. Last-arriving split per batch merges and writes
// the output. All counters self-reset for graph replay.
__global__ void __launch_bounds__(256, 1)
attn_persist(const float* __restrict__ enc, const float* __restrict__ hn,
             float* __restrict__ out)
{
    extern __shared__ char smem[];
    const int tid = threadIdx.x;
    const int wid = tid >> 5;
    const int ln  = tid & 31;

    const uint32_t sbase = smem_u32(smem);
    const uint32_t mbar0 = sbase + MBAR_OFF;
    float* msh   = (float*)(smem + META_OFF);        // [8] warp maxes
    float* lsh   = msh + 8;                          // [8] warp sums
    int*   flags = (int*)(msh + 16);                 // [0]=last flag
    int*   it_ring = flags + 1;                      // [2] in-flight item ids
    float4* comb = (float4*)(smem + COMB_OFF);       // 32KB combine scratch

    if (tid == 0) {
#pragma unroll
        for (int s = 0; s < NBUF; s++) MBARRIER_INIT(mbar0 + 8 * s, 1);
        it_ring[0] = atomicAdd(&g_work, 1);
        it_ring[1] = TOTAL_ITEMS;
    }
    __syncthreads();

    // Prologue: fill pipeline with stages 0..2 of item 0 (NSTAGES=8 >= NBUF)
    if (tid == 0) {
        const int i0 = it_ring[0];
        if (i0 < TOTAL_ITEMS) {
            const char* src = item_src(enc, i0);
#pragma unroll
            for (int s = 0; s < NBUF; s++) {
                MBARRIER_EXPECT_TX(mbar0 + 8 * s, STAGE_BYTES);
                BULK_G2S(sbase + s * STAGE_BYTES, src + (size_t)s * STAGE_BYTES,
                         STAGE_BYTES, mbar0 + 8 * s);
            }
        }
    }
    __syncthreads();

    const float4* bufs = (const float4*)smem;

    for (int c = 0;; c++) {
        const int item = it_ring[c & 1];
        if (item >= TOTAL_ITEMS) break;
        const int b = item >> 4;
        const int sp = item & (NSPLIT - 1);

        // h_n[b] into registers (per-lane column map)
        const float4* h4 = (const float4*)(hn + (size_t)b * H_DIM);
        float4 hreg[8];
#pragma unroll
        for (int i = 0; i < 8; i++) hreg[i] = h4[i * 32 + ln];

        float m = -CUDART_INF_F;
        float l = 0.f;
        float4 acc[8];
#pragma unroll
        for (int i = 0; i < 8; i++) acc[i] = make_float4(0.f, 0.f, 0.f, 0.f);

        for (int st = 0; st < NSTAGES; st++) {
            const int g    = c * NSTAGES + st;       // global stage index
            const int bsel = g % NBUF;
            const int par  = (g / NBUF) & 1;
            MBARRIER_WAIT_PARITY(mbar0 + 8 * bsel, par);
            const float4* tile = bufs + (size_t)bsel * (STAGE_ROWS * (H_DIM / 4));

#pragma unroll
            for (int rr = 0; rr < 2; rr++) {
                const float4* row = tile + (size_t)(wid * 2 + rr) * (H_DIM / 4);
                float4 v[8];
#pragma unroll
                for (int i = 0; i < 8; i++) v[i] = row[i * 32 + ln];

                float d = 0.f;
#pragma unroll
                for (int i = 0; i < 8; i++) {
                    d += v[i].x * hreg[i].x + v[i].y * hreg[i].y
                       + v[i].z * hreg[i].z + v[i].w * hreg[i].w;
                }
#pragma unroll
                for (int off = 16; off; off >>= 1)
                    d += __shfl_xor_sync(0xffffffffu, d, off);

                const float mn = fmaxf(m, d);
                const float cf = __expf(m - mn);
                const float w  = __expf(d - mn);
                m = mn;
                l = l * cf + w;
#pragma unroll
                for (int i = 0; i < 8; i++) {
                    acc[i].x = acc[i].x * cf + w * v[i].x;
                    acc[i].y = acc[i].y * cf + w * v[i].y;
                    acc[i].z = acc[i].z * cf + w * v[i].z;
                    acc[i].w = acc[i].w * cf + w * v[i].w;
                }
            }
            __syncthreads();   // buffer bsel free for reuse

            // Issue stage g+NBUF; claim a new item when lookahead crosses a boundary
            if (tid == 0) {
                const int G = g + NBUF;
                const int ridx = (G >> 3) & 1;       // (G / NSTAGES) & 1
                if ((G & (NSTAGES - 1)) == 0)
                    it_ring[ridx] = atomicAdd(&g_work, 1);
                const int gi = it_ring[ridx];
                if (gi < TOTAL_ITEMS) {
                    const int gb = G % NBUF;
                    MBARRIER_EXPECT_TX(mbar0 + 8 * gb, STAGE_BYTES);
                    BULK_G2S(sbase + gb * STAGE_BYTES,
                             item_src(enc, gi) + (size_t)(G & (NSTAGES - 1)) * STAGE_BYTES,
                             STAGE_BYTES, mbar0 + 8 * gb);
                }
            }
        }

        // ---- Epilogue for this item: combine 8 warp partials ----
        if (ln == 0) { msh[wid] = m; lsh[wid] = l; }
        __syncthreads();

        float M = msh[0];
#pragma unroll
        for (int w2 = 1; w2 < 8; w2++) M = fmaxf(M, msh[w2]);
        float L = 0.f;
#pragma unroll
        for (int w2 = 0; w2 < 8; w2++) L += lsh[w2] * __expf(msh[w2] - M);
        const float f = __expf(m - M);

#pragma unroll
        for (int i = 0; i < 8; i++) {
            float4 t;
            t.x = acc[i].x * f; t.y = acc[i].y * f;
            t.z = acc[i].z * f; t.w = acc[i].w * f;
            comb[wid * 256 + i * 32 + ln] = t;
        }
        __syncthreads();

        float4 s = comb[tid];
#pragma unroll
        for (int w2 = 1; w2 < 8; w2++) {
            const float4 t = comb[w2 * 256 + tid];
            s.x += t.x; s.y += t.y; s.z += t.z; s.w += t.w;
        }
        ((float4*)g_num)[(size_t)(b * NSPLIT + sp) * 256 + tid] = s;
        if (tid == 0) {
            g_ml[(b * NSPLIT + sp) * 2 + 0] = M;
            g_ml[(b * NSPLIT + sp) * 2 + 1] = L;
        }

        // ---- Last split of this batch merges all NSPLIT partials ----
        __threadfence();
        if (tid == 0) {
            const int cc = atomicAdd(&g_cnt[b], 1);
            const int last = (cc == NSPLIT - 1);
            if (last) g_cnt[b] = 0;                  // self-reset for next replay
            flags[0] = last;
        }
        __syncthreads();
        if (flags[0]) {
            __threadfence();
            float ml_m[NSPLIT], ml_l[NSPLIT];
#pragma unroll
            for (int s2 = 0; s2 < NSPLIT; s2++) {
                ml_m[s2] = g_ml[(b * NSPLIT + s2) * 2 + 0];
                ml_l[s2] = g_ml[(b * NSPLIT + s2) * 2 + 1];
            }
            float GM = ml_m[0];
#pragma unroll
            for (int s2 = 1; s2 < NSPLIT; s2++) GM = fmaxf(GM, ml_m[s2]);
            float GL = 0.f;
#pragma unroll
            for (int s2 = 0; s2 < NSPLIT; s2++) GL += ml_l[s2] * __expf(ml_m[s2] - GM);

            float4 a = make_float4(0.f, 0.f, 0.f, 0.f);
            const float4* num4 = (const float4*)g_num;
#pragma unroll
            for (int s2 = 0; s2 < NSPLIT; s2++) {
                const float fs = __expf(ml_m[s2] - GM);
                const float4 t = num4[(size_t)(b * NSPLIT + s2) * 256 + tid];
                a.x += fs * t.x; a.y += fs * t.y; a.z += fs * t.z; a.w += fs * t.w;
            }
            const float inv = 1.0f / GL;

            float4* out4 = (float4*)out;
            out4[(size_t)b * 512 + tid] = ((const float4*)(hn + (size_t)b * H_DIM))[tid];
            float4 ctx;
            ctx.x = a.x * inv; ctx.y = a.y * inv;
            ctx.z = a.z * inv; ctx.w = a.w * inv;
            out4[(size_t)b * 512 + 256 + tid] = ctx;
        }
        __syncthreads();   // comb/flags safe for next item
    }

    // ---- Self-reset of work-stealing counters (last CTA to finish) ----
    if (tid == 0) {
        __threadfence();
        const int d = atomicAdd(&g_done, 1);
        if (d == (int)gridDim.x - 1) {
            g_work = 0;
            g_done = 0;
        }
    }
}

// ---------------- Launch ----------------
extern "C" void kernel_launch(void* const* d_in, const int* in_sizes, int n_in,
                              void* d_out, int out_size)
{
    const float* enc = (const float*)d_in[0];   // (64, 2048, 1024) f32
    const float* hn  = (const float*)d_in[1];   // (64, 1024) f32
    float* out = (float*)d_out;                 // (64, 1, 2048) f32

    cudaFuncSetAttribute(attn_persist,
                         cudaFuncAttributeMaxDynamicSharedMemorySize, SMEM_TOTAL);

    attn_persist<<<GRID, 256, SMEM_TOTAL>>>(enc, hn, out);
}

// round 4
// speedup vs baseline: 1.0627x; 1.0627x over previous
#include <cuda_runtime.h>
#include <cstdint>
#include <math_constants.h>

// Problem constants
#define BATCH      64
#define SEQ        2048
#define H_DIM      1024
#define NSPLIT     8
#define ROWS_PER_CTA (SEQ / NSPLIT)            // 256
#define STAGE_ROWS 16
#define NSTAGES    (ROWS_PER_CTA / STAGE_ROWS) // 16
#define NBUF       3
#define STAGE_BYTES (STAGE_ROWS * H_DIM * 4)   // 65536
#define SMEM_BUF_BYTES (NBUF * STAGE_BYTES)    // 196608
#define SMEM_TOTAL (SMEM_BUF_BYTES + 128)

typedef unsigned long long u64;

// Cross-CTA scratch (allocation-free: __device__ globals, zero-initialized)
__device__ float g_num[BATCH * NSPLIT * H_DIM];   // per-split exp-weighted numerator
__device__ float g_ml[BATCH * NSPLIT * 2];        // per-split (M, L)
__device__ int   g_cnt[BATCH];                    // arrival counters (self-resetting)

// ---------------- PTX helpers ----------------
__device__ __forceinline__ uint32_t smem_u32(const void* p) {
    uint32_t a;
    asm("{ .reg .u64 t; cvta.to.shared.u64 t, %1; cvt.u32.u64 %0, t; }"
        : "=r"(a) : "l"(p));
    return a;
}

// Packed f32x2 ops (Blackwell FFMA2 — only reachable via PTX)
__device__ __forceinline__ u64 fma2(u64 a, u64 b, u64 c) {
    u64 d; asm("fma.rn.f32x2 %0, %1, %2, %3;" : "=l"(d) : "l"(a), "l"(b), "l"(c));
    return d;
}
__device__ __forceinline__ u64 add2(u64 a, u64 b) {
    u64 d; asm("add.rn.f32x2 %0, %1, %2;" : "=l"(d) : "l"(a), "l"(b));
    return d;
}
__device__ __forceinline__ u64 pack2(float lo, float hi) {
    u64 r; asm("mov.b64 %0, {%1, %2};" : "=l"(r) : "f"(lo), "f"(hi));
    return r;
}
__device__ __forceinline__ void unpack2(u64 v, float& lo, float& hi) {
    asm("mov.b64 {%0, %1}, %2;" : "=f"(lo), "=f"(hi) : "l"(v));
}

#define MBARRIER_INIT(addr, count) \
    asm volatile("mbarrier.init.shared.b64 [%0], %1;" \
                 :: "r"((uint32_t)(addr)), "r"((uint32_t)(count)) : "memory")

#define MBARRIER_EXPECT_TX(addr, bytes) \
    asm volatile("mbarrier.arrive.expect_tx.shared.b64 _, [%0], %1;" \
                 :: "r"((uint32_t)(addr)), "r"((uint32_t)(bytes)) : "memory")

#define MBARRIER_WAIT_PARITY(mbar_smem_addr, phase_parity) do { \
    uint32_t _mbar = (uint32_t)(mbar_smem_addr); \
    uint32_t _parity = (uint32_t)(phase_parity); \
    uint32_t _done; \
    asm volatile( \
        "{\n\t" \
        ".reg .pred p;\n\t" \
        "mbarrier.try_wait.parity.acquire.cta.shared::cta.b64 p, [%1], %2;\n\t" \
        "selp.b32 %0, 1, 0, p;\n\t" \
        "}" \
        : "=r"(_done) : "r"(_mbar), "r"(_parity) : "memory"); \
    if (!_done) { \
        asm volatile( \
            "{\n\t" \
            ".reg .pred P1;\n\t" \
            "WAIT_LOOP_%=:\n\t" \
            "mbarrier.try_wait.parity.acquire.cta.shared::cta.b64 P1, [%0], %1, 0x989680;\n\t" \
            "@P1 bra.uni WAIT_DONE_%=;\n\t" \
            "bra.uni WAIT_LOOP_%=;\n\t" \
            "WAIT_DONE_%=:\n\t" \
            "}" \
            :: "r"(_mbar), "r"(_parity) : "memory"); \
    } \
} while (0)

#define BULK_G2S(dst_smem, src_gmem, nbytes, mbar) \
    asm volatile("cp.async.bulk.shared::cluster.global.mbarrier::complete_tx::bytes " \
                 "[%0], [%1], %2, [%3];" \
                 :: "r"((uint32_t)(dst_smem)), "l"(src_gmem), \
                    "r"((uint32_t)(nbytes)), "r"((uint32_t)(mbar)) : "memory")

// ---------------- Fused split-KV online softmax + last-CTA combine ----------------
// grid = 512 CTAs (64 batches x 8 splits), 256 threads. Each CTA streams 256
// contiguous seq rows (1 MiB) through a 3-deep cp.async.bulk pipeline.
// Warp w handles rows {w*2, w*2+1} of each 16-row stage.
// Lane l owns packed column pairs of {l*4 + i*128 + j : i in 0..7, j in 0..3}.
// Inner loop uses fma.rn.f32x2 (2 elts/instr) and a warp-uniform rare-rescale
// branch: 32 FMA-pipe instrs per row per lane total (was ~96 scalar FFMA).
__global__ void __launch_bounds__(256, 1)
attn_fused(const float* __restrict__ enc, const float* __restrict__ hn,
           float* __restrict__ out)
{
    extern __shared__ char smem[];
    const int tid = threadIdx.x;
    const int wid = tid >> 5;
    const int ln  = tid & 31;
    const int b   = blockIdx.x / NSPLIT;
    const int sp  = blockIdx.x % NSPLIT;

    const char* src_base =
        (const char*)(enc + ((size_t)b * SEQ + (size_t)sp * ROWS_PER_CTA) * H_DIM);

    const uint32_t sbase = smem_u32(smem);
    const uint32_t mbar0 = sbase + SMEM_BUF_BYTES;
    float* msh = (float*)(smem + SMEM_BUF_BYTES + 32);
    float* lsh = msh + 8;
    int* lastsh = (int*)(msh + 16);

    if (tid == 0) {
#pragma unroll
        for (int s = 0; s < NBUF; s++) MBARRIER_INIT(mbar0 + 8 * s, 1);
    }
    __syncthreads();

    // h_n[b] as packed f32x2 pairs matching the per-lane column map
    const ulonglong2* h2 = (const ulonglong2*)(hn + (size_t)b * H_DIM);
    ulonglong2 hreg[8];
#pragma unroll
    for (int i = 0; i < 8; i++) hreg[i] = h2[i * 32 + ln];

    float m = -CUDART_INF_F;
    float l = 0.f;
    u64 acc[16];
#pragma unroll
    for (int i = 0; i < 16; i++) acc[i] = 0ull;    // two packed +0.0f

    // Prologue: fill the pipeline
    if (tid == 0) {
#pragma unroll
        for (int s = 0; s < NBUF; s++) {
            MBARRIER_EXPECT_TX(mbar0 + 8 * s, STAGE_BYTES);
            BULK_G2S(sbase + s * STAGE_BYTES,
                     src_base + (size_t)s * STAGE_BYTES,
                     STAGE_BYTES, mbar0 + 8 * s);
        }
    }

    for (int st = 0; st < NSTAGES; st++) {
        const int bsel = st % NBUF;
        const int par  = (st / NBUF) & 1;
        MBARRIER_WAIT_PARITY(mbar0 + 8 * bsel, par);

#pragma unroll
        for (int rr = 0; rr < 2; rr++) {
            const ulonglong2* row = (const ulonglong2*)
                (smem + (size_t)bsel * STAGE_BYTES + (size_t)(wid * 2 + rr) * (H_DIM * 4));
            ulonglong2 v[8];
#pragma unroll
            for (int i = 0; i < 8; i++) v[i] = row[i * 32 + ln];   // 16B lane stride: conflict-free

            // Packed dot: 16 fma2, 2 independent chains
            u64 p0 = 0ull, p1 = 0ull;
#pragma unroll
            for (int i = 0; i < 8; i++) {
                p0 = fma2(v[i].x, hreg[i].x, p0);
                p1 = fma2(v[i].y, hreg[i].y, p1);
            }
            float dl, dh;
            unpack2(add2(p0, p1), dl, dh);
            float d = dl + dh;
#pragma unroll
            for (int off = 16; off; off >>= 1)
                d += __shfl_xor_sync(0xffffffffu, d, off);

            // Warp-uniform branch: d identical across lanes
            if (d > m) {
                const float cf = __expf(m - d);    // exp(-inf)=0 on first row
                m = d;
                l = l * cf + 1.f;
                const u64 cf2 = pack2(cf, cf);
#pragma unroll
                for (int i = 0; i < 8; i++) {      // acc = acc*cf + v  (one fma2)
                    acc[2 * i]     = fma2(acc[2 * i],     cf2, v[i].x);
                    acc[2 * i + 1] = fma2(acc[2 * i + 1], cf2, v[i].y);
                }
            } else {
                const float w = __expf(d - m);
                l += w;
                const u64 w2 = pack2(w, w);
#pragma unroll
                for (int i = 0; i < 8; i++) {      // acc += w*v  (one fma2)
                    acc[2 * i]     = fma2(v[i].x, w2, acc[2 * i]);
                    acc[2 * i + 1] = fma2(v[i].y, w2, acc[2 * i + 1]);
                }
            }
        }
        __syncthreads();   // all warps done with buffer bsel
        if (tid == 0 && st + NBUF < NSTAGES) {
            MBARRIER_EXPECT_TX(mbar0 + 8 * bsel, STAGE_BYTES);
            BULK_G2S(sbase + bsel * STAGE_BYTES,
                     src_base + (size_t)(st + NBUF) * STAGE_BYTES,
                     STAGE_BYTES, mbar0 + 8 * bsel);
        }
    }

    // ---- Combine 8 warp partials within the CTA ----
    if (ln == 0) { msh[wid] = m; lsh[wid] = l; }
    __syncthreads();

    float M = msh[0];
#pragma unroll
    for (int w2i = 1; w2i < 8; w2i++) M = fmaxf(M, msh[w2i]);
    float L = 0.f;
#pragma unroll
    for (int w2i = 0; w2i < 8; w2i++) L += lsh[w2i] * __expf(msh[w2i] - M);
    const float f = __expf(m - M);

    // Reuse stage buffer 0 as [8 warps][256 float4] combine scratch (32 KiB)
    // (no TMA in flight: issues stopped at st+NBUF >= NSTAGES)
    float4* comb = (float4*)smem;
#pragma unroll
    for (int i = 0; i < 8; i++) {
        float ax, ay, az, aw;
        unpack2(acc[2 * i],     ax, ay);
        unpack2(acc[2 * i + 1], az, aw);
        float4 t;
        t.x = ax * f; t.y = ay * f; t.z = az * f; t.w = aw * f;
        comb[wid * 256 + i * 32 + ln] = t;
    }
    __syncthreads();

    float4 s = comb[tid];
#pragma unroll
    for (int w2i = 1; w2i < 8; w2i++) {
        const float4 t = comb[w2i * 256 + tid];
        s.x += t.x; s.y += t.y; s.z += t.z; s.w += t.w;
    }
    ((float4*)g_num)[(size_t)(b * NSPLIT + sp) * 256 + tid] = s;
    if (tid == 0) {
        g_ml[(b * NSPLIT + sp) * 2 + 0] = M;
        g_ml[(b * NSPLIT + sp) * 2 + 1] = L;
    }

    // ---- Last CTA of this batch merges all NSPLIT splits ----
    __threadfence();
    if (tid == 0) {
        const int c = atomicAdd(&g_cnt[b], 1);
        const int last = (c == NSPLIT - 1);
        if (last) g_cnt[b] = 0;      // self-reset for next graph replay
        *lastsh = last;
    }
    __syncthreads();
    if (!*lastsh) return;
    __threadfence();

    // Merge (L2-hot: 32 KiB numerators + 64 B of (M,L) for this batch)
    float ml_m[NSPLIT], ml_l[NSPLIT];
#pragma unroll
    for (int s2 = 0; s2 < NSPLIT; s2++) {
        ml_m[s2] = g_ml[(b * NSPLIT + s2) * 2 + 0];
        ml_l[s2] = g_ml[(b * NSPLIT + s2) * 2 + 1];
    }
    float GM = ml_m[0];
#pragma unroll
    for (int s2 = 1; s2 < NSPLIT; s2++) GM = fmaxf(GM, ml_m[s2]);
    float GL = 0.f;
#pragma unroll
    for (int s2 = 0; s2 < NSPLIT; s2++) GL += ml_l[s2] * __expf(ml_m[s2] - GM);

    float4 a = make_float4(0.f, 0.f, 0.f, 0.f);
    const float4* num4 = (const float4*)g_num;
#pragma unroll
    for (int s2 = 0; s2 < NSPLIT; s2++) {
        const float fs = __expf(ml_m[s2] - GM);
        const float4 t = num4[(size_t)(b * NSPLIT + s2) * 256 + tid];
        a.x += fs * t.x; a.y += fs * t.y; a.z += fs * t.z; a.w += fs * t.w;
    }
    const float inv = 1.0f / GL;

    float4* out4 = (float4*)out;
    out4[(size_t)b * 512 + tid] = ((const float4*)(hn + (size_t)b * H_DIM))[tid];
    float4 ctx;
    ctx.x = a.x * inv; ctx.y = a.y * inv; ctx.z = a.z * inv; ctx.w = a.w * inv;
    out4[(size_t)b * 512 + 256 + tid] = ctx;
}

// ---------------- Launch ----------------
extern "C" void kernel_launch(void* const* d_in, const int* in_sizes, int n_in,
                              void* d_out, int out_size)
{
    const float* enc = (const float*)d_in[0];   // (64, 2048, 1024) f32
    const float* hn  = (const float*)d_in[1];   // (64, 1024) f32
    float* out = (float*)d_out;                 // (64, 1, 2048) f32

    cudaFuncSetAttribute(attn_fused,
                         cudaFuncAttributeMaxDynamicSharedMemorySize, SMEM_TOTAL);

    attn_fused<<<BATCH * NSPLIT, 256, SMEM_TOTAL>>>(enc, hn, out);
}

// round 5
// speedup vs baseline: 1.0692x; 1.0061x over previous
#include <cuda_runtime.h>
#include <cstdint>
#include <math_constants.h>

// Problem constants
#define BATCH      64
#define SEQ        2048
#define H_DIM      1024
#define NSPLIT     8
#define ROWS_PER_CTA (SEQ / NSPLIT)            // 256
#define STAGE_ROWS 16
#define NSTAGES    (ROWS_PER_CTA / STAGE_ROWS) // 16
#define NBUF       3
#define STAGE_BYTES (STAGE_ROWS * H_DIM * 4)   // 65536
#define SMEM_BUF_BYTES (NBUF * STAGE_BYTES)    // 196608
#define SMEM_TOTAL (SMEM_BUF_BYTES + 128)
#define WORK_CTAS  (BATCH * NSPLIT)            // 512
#define GRID       (WORK_CTAS + BATCH)         // 512 work + 64 combine

typedef unsigned long long u64;

// Cross-CTA scratch (allocation-free: __device__ globals, zero-initialized)
__device__ float g_num[BATCH * NSPLIT * H_DIM];   // per-split exp-weighted numerator
__device__ float g_ml[BATCH * NSPLIT * 2];        // per-split (M, L)
__device__ int   g_cnt[BATCH];                    // arrival counters (combine CTA resets)

// ---------------- PTX helpers ----------------
__device__ __forceinline__ uint32_t smem_u32(const void* p) {
    uint32_t a;
    asm("{ .reg .u64 t; cvta.to.shared.u64 t, %1; cvt.u32.u64 %0, t; }"
        : "=r"(a) : "l"(p));
    return a;
}

// Packed f32x2 ops (Blackwell FFMA2 — only reachable via PTX)
__device__ __forceinline__ u64 fma2(u64 a, u64 b, u64 c) {
    u64 d; asm("fma.rn.f32x2 %0, %1, %2, %3;" : "=l"(d) : "l"(a), "l"(b), "l"(c));
    return d;
}
__device__ __forceinline__ u64 add2(u64 a, u64 b) {
    u64 d; asm("add.rn.f32x2 %0, %1, %2;" : "=l"(d) : "l"(a), "l"(b));
    return d;
}
__device__ __forceinline__ u64 pack2(float lo, float hi) {
    u64 r; asm("mov.b64 %0, {%1, %2};" : "=l"(r) : "f"(lo), "f"(hi));
    return r;
}
__device__ __forceinline__ void unpack2(u64 v, float& lo, float& hi) {
    asm("mov.b64 {%0, %1}, %2;" : "=f"(lo), "=f"(hi) : "l"(v));
}

#define MBARRIER_INIT(addr, count) \
    asm volatile("mbarrier.init.shared.b64 [%0], %1;" \
                 :: "r"((uint32_t)(addr)), "r"((uint32_t)(count)) : "memory")

#define MBARRIER_EXPECT_TX(addr, bytes) \
    asm volatile("mbarrier.arrive.expect_tx.shared.b64 _, [%0], %1;" \
                 :: "r"((uint32_t)(addr)), "r"((uint32_t)(bytes)) : "memory")

#define MBARRIER_WAIT_PARITY(mbar_smem_addr, phase_parity) do { \
    uint32_t _mbar = (uint32_t)(mbar_smem_addr); \
    uint32_t _parity = (uint32_t)(phase_parity); \
    uint32_t _done; \
    asm volatile( \
        "{\n\t" \
        ".reg .pred p;\n\t" \
        "mbarrier.try_wait.parity.acquire.cta.shared::cta.b64 p, [%1], %2;\n\t" \
        "selp.b32 %0, 1, 0, p;\n\t" \
        "}" \
        : "=r"(_done) : "r"(_mbar), "r"(_parity) : "memory"); \
    if (!_done) { \
        asm volatile( \
            "{\n\t" \
            ".reg .pred P1;\n\t" \
            "WAIT_LOOP_%=:\n\t" \
            "mbarrier.try_wait.parity.acquire.cta.shared::cta.b64 P1, [%0], %1, 0x989680;\n\t" \
            "@P1 bra.uni WAIT_DONE_%=;\n\t" \
            "bra.uni WAIT_LOOP_%=;\n\t" \
            "WAIT_DONE_%=:\n\t" \
            "}" \
            :: "r"(_mbar), "r"(_parity) : "memory"); \
    } \
} while (0)

#define BULK_G2S(dst_smem, src_gmem, nbytes, mbar) \
    asm volatile("cp.async.bulk.shared::cluster.global.mbarrier::complete_tx::bytes " \
                 "[%0], [%1], %2, [%3];" \
                 :: "r"((uint32_t)(dst_smem)), "l"(src_gmem), \
                    "r"((uint32_t)(nbytes)), "r"((uint32_t)(mbar)) : "memory")

// ---------------- One kernel, two roles ----------------
// blockIdx < 512: work CTA — stream 256 seq rows (1 MiB) through a 3-deep
//   cp.async.bulk pipeline, online softmax with fma.rn.f32x2, write per-split
//   partials (g_num, g_ml), signal g_cnt[b]. NO merge in the wave path.
// blockIdx >= 512: combine CTA for batch b — scheduled in the LAST wave by
//   block ordering; spin-waits for its 8 splits, merges from L2, writes output.
//   Overlaps with the final work wave instead of serializing every wave.
__global__ void __launch_bounds__(256, 1)
attn_kernel(const float* __restrict__ enc, const float* __restrict__ hn,
            float* __restrict__ out)
{
    const int tid = threadIdx.x;

    // ================= Combine role =================
    if (blockIdx.x >= WORK_CTAS) {
        const int b = blockIdx.x - WORK_CTAS;
        __shared__ int ready;
        if (tid == 0) {
            while (atomicAdd(&g_cnt[b], 0) != NSPLIT) __nanosleep(200);
            g_cnt[b] = 0;                 // self-reset for next graph replay
            ready = 1;
        }
        __syncthreads();
        (void)ready;
        __threadfence();                  // acquire partials

        float ml_m[NSPLIT], ml_l[NSPLIT];
#pragma unroll
        for (int s2 = 0; s2 < NSPLIT; s2++) {
            ml_m[s2] = g_ml[(b * NSPLIT + s2) * 2 + 0];
            ml_l[s2] = g_ml[(b * NSPLIT + s2) * 2 + 1];
        }
        float GM = ml_m[0];
#pragma unroll
        for (int s2 = 1; s2 < NSPLIT; s2++) GM = fmaxf(GM, ml_m[s2]);
        float GL = 0.f;
#pragma unroll
        for (int s2 = 0; s2 < NSPLIT; s2++) GL += ml_l[s2] * __expf(ml_m[s2] - GM);

        float4 a = make_float4(0.f, 0.f, 0.f, 0.f);
        const float4* num4 = (const float4*)g_num;
#pragma unroll
        for (int s2 = 0; s2 < NSPLIT; s2++) {
            const float fs = __expf(ml_m[s2] - GM);
            const float4 t = num4[(size_t)(b * NSPLIT + s2) * 256 + tid];
            a.x += fs * t.x; a.y += fs * t.y; a.z += fs * t.z; a.w += fs * t.w;
        }
        const float inv = 1.0f / GL;

        float4* out4 = (float4*)out;
        out4[(size_t)b * 512 + tid] = ((const float4*)(hn + (size_t)b * H_DIM))[tid];
        float4 ctx;
        ctx.x = a.x * inv; ctx.y = a.y * inv; ctx.z = a.z * inv; ctx.w = a.w * inv;
        out4[(size_t)b * 512 + 256 + tid] = ctx;
        return;
    }

    // ================= Work role =================
    extern __shared__ char smem[];
    const int wid = tid >> 5;
    const int ln  = tid & 31;
    const int b   = blockIdx.x / NSPLIT;
    const int sp  = blockIdx.x % NSPLIT;

    const char* src_base =
        (const char*)(enc + ((size_t)b * SEQ + (size_t)sp * ROWS_PER_CTA) * H_DIM);

    const uint32_t sbase = smem_u32(smem);
    const uint32_t mbar0 = sbase + SMEM_BUF_BYTES;
    float* msh = (float*)(smem + SMEM_BUF_BYTES + 32);
    float* lsh = msh + 8;

    if (tid == 0) {
#pragma unroll
        for (int s = 0; s < NBUF; s++) MBARRIER_INIT(mbar0 + 8 * s, 1);
    }
    __syncthreads();

    // h_n[b] as packed f32x2 pairs matching the per-lane column map
    const ulonglong2* h2 = (const ulonglong2*)(hn + (size_t)b * H_DIM);
    ulonglong2 hreg[8];
#pragma unroll
    for (int i = 0; i < 8; i++) hreg[i] = h2[i * 32 + ln];

    float m = -CUDART_INF_F;
    float l = 0.f;
    u64 acc[16];
#pragma unroll
    for (int i = 0; i < 16; i++) acc[i] = 0ull;

    // Prologue: fill the pipeline
    if (tid == 0) {
#pragma unroll
        for (int s = 0; s < NBUF; s++) {
            MBARRIER_EXPECT_TX(mbar0 + 8 * s, STAGE_BYTES);
            BULK_G2S(sbase + s * STAGE_BYTES,
                     src_base + (size_t)s * STAGE_BYTES,
                     STAGE_BYTES, mbar0 + 8 * s);
        }
    }

    for (int st = 0; st < NSTAGES; st++) {
        const int bsel = st % NBUF;
        const int par  = (st / NBUF) & 1;
        MBARRIER_WAIT_PARITY(mbar0 + 8 * bsel, par);

#pragma unroll
        for (int rr = 0; rr < 2; rr++) {
            const ulonglong2* row = (const ulonglong2*)
                (smem + (size_t)bsel * STAGE_BYTES + (size_t)(wid * 2 + rr) * (H_DIM * 4));
            ulonglong2 v[8];
#pragma unroll
            for (int i = 0; i < 8; i++) v[i] = row[i * 32 + ln];   // 16B lane stride: conflict-free

            // Packed dot: 16 fma2, 2 independent chains
            u64 p0 = 0ull, p1 = 0ull;
#pragma unroll
            for (int i = 0; i < 8; i++) {
                p0 = fma2(v[i].x, hreg[i].x, p0);
                p1 = fma2(v[i].y, hreg[i].y, p1);
            }
            float dl, dh;
            unpack2(add2(p0, p1), dl, dh);
            float d = dl + dh;
#pragma unroll
            for (int off = 16; off; off >>= 1)
                d += __shfl_xor_sync(0xffffffffu, d, off);

            // Warp-uniform branch: d identical across lanes
            if (d > m) {
                const float cf = __expf(m - d);    // exp(-inf)=0 on first row
                m = d;
                l = l * cf + 1.f;
                const u64 cf2 = pack2(cf, cf);
#pragma unroll
                for (int i = 0; i < 8; i++) {
                    acc[2 * i]     = fma2(acc[2 * i],     cf2, v[i].x);
                    acc[2 * i + 1] = fma2(acc[2 * i + 1], cf2, v[i].y);
                }
            } else {
                const float w = __expf(d - m);
                l += w;
                const u64 w2 = pack2(w, w);
#pragma unroll
                for (int i = 0; i < 8; i++) {
                    acc[2 * i]     = fma2(v[i].x, w2, acc[2 * i]);
                    acc[2 * i + 1] = fma2(v[i].y, w2, acc[2 * i + 1]);
                }
            }
        }
        __syncthreads();   // all warps done with buffer bsel
        if (tid == 0 && st + NBUF < NSTAGES) {
            MBARRIER_EXPECT_TX(mbar0 + 8 * bsel, STAGE_BYTES);
            BULK_G2S(sbase + bsel * STAGE_BYTES,
                     src_base + (size_t)(st + NBUF) * STAGE_BYTES,
                     STAGE_BYTES, mbar0 + 8 * bsel);
        }
    }

    // ---- Combine 8 warp partials within the CTA, write split partials ----
    if (ln == 0) { msh[wid] = m; lsh[wid] = l; }
    __syncthreads();

    float M = msh[0];
#pragma unroll
    for (int w2i = 1; w2i < 8; w2i++) M = fmaxf(M, msh[w2i]);
    float L = 0.f;
#pragma unroll
    for (int w2i = 0; w2i < 8; w2i++) L += lsh[w2i] * __expf(msh[w2i] - M);
    const float f = __expf(m - M);

    // Reuse stage buffer 0 as [8 warps][256 float4] combine scratch (32 KiB)
    float4* comb = (float4*)smem;
#pragma unroll
    for (int i = 0; i < 8; i++) {
        float ax, ay, az, aw;
        unpack2(acc[2 * i],     ax, ay);
        unpack2(acc[2 * i + 1], az, aw);
        float4 t;
        t.x = ax * f; t.y = ay * f; t.z = az * f; t.w = aw * f;
        comb[wid * 256 + i * 32 + ln] = t;
    }
    __syncthreads();

    float4 s = comb[tid];
#pragma unroll
    for (int w2i = 1; w2i < 8; w2i++) {
        const float4 t = comb[w2i * 256 + tid];
        s.x += t.x; s.y += t.y; s.z += t.z; s.w += t.w;
    }
    ((float4*)g_num)[(size_t)(b * NSPLIT + sp) * 256 + tid] = s;
    if (tid == 0) {
        g_ml[(b * NSPLIT + sp) * 2 + 0] = M;
        g_ml[(b * NSPLIT + sp) * 2 + 1] = L;
        __threadfence();                      // release partials
        atomicAdd(&g_cnt[b], 1);              // signal combine CTA
    }
}

// ---------------- Launch ----------------
extern "C" void kernel_launch(void* const* d_in, const int* in_sizes, int n_in,
                              void* d_out, int out_size)
{
    const float* enc = (const float*)d_in[0];   // (64, 2048, 1024) f32
    const float* hn  = (const float*)d_in[1];   // (64, 1024) f32
    float* out = (float*)d_out;                 // (64, 1, 2048) f32

    cudaFuncSetAttribute(attn_kernel,
                         cudaFuncAttributeMaxDynamicSharedMemorySize, SMEM_TOTAL);

    attn_kernel<<<GRID, 256, SMEM_TOTAL>>>(enc, hn, out);
}

// round 6
// speedup vs baseline: 1.1213x; 1.0487x over previous
#include <cuda_runtime.h>
#include <cstdint>
#include <math_constants.h>

// Problem constants
#define BATCH      64
#define SEQ        2048
#define H_DIM      1024
#define NSPLIT     8
#define ROWS_PER_CTA (SEQ / NSPLIT)            // 256
#define STAGE_ROWS 8
#define NSTAGES    (ROWS_PER_CTA / STAGE_ROWS) // 32
#define NBUF       3
#define STAGE_BYTES (STAGE_ROWS * H_DIM * 4)   // 32768
#define SMEM_BUF_BYTES (NBUF * STAGE_BYTES)    // 98304
#define SMEM_TOTAL (SMEM_BUF_BYTES + 128)      // 98432 -> 2 CTAs/SM fit (196864 <= ~227KB)
#define WORK_CTAS  (BATCH * NSPLIT)            // 512
#define GRID       (WORK_CTAS + BATCH)         // 512 work + 64 combine

typedef unsigned long long u64;

// Cross-CTA scratch (allocation-free: __device__ globals, zero-initialized)
__device__ float g_num[BATCH * NSPLIT * H_DIM];   // per-split exp-weighted numerator
__device__ float g_ml[BATCH * NSPLIT * 2];        // per-split (M, L)
__device__ int   g_cnt[BATCH];                    // arrival counters (combine CTA resets)

// ---------------- PTX helpers ----------------
__device__ __forceinline__ uint32_t smem_u32(const void* p) {
    uint32_t a;
    asm("{ .reg .u64 t; cvta.to.shared.u64 t, %1; cvt.u32.u64 %0, t; }"
        : "=r"(a) : "l"(p));
    return a;
}

// Packed f32x2 ops (Blackwell FFMA2 — only reachable via PTX)
__device__ __forceinline__ u64 fma2(u64 a, u64 b, u64 c) {
    u64 d; asm("fma.rn.f32x2 %0, %1, %2, %3;" : "=l"(d) : "l"(a), "l"(b), "l"(c));
    return d;
}
__device__ __forceinline__ u64 add2(u64 a, u64 b) {
    u64 d; asm("add.rn.f32x2 %0, %1, %2;" : "=l"(d) : "l"(a), "l"(b));
    return d;
}
__device__ __forceinline__ u64 pack2(float lo, float hi) {
    u64 r; asm("mov.b64 %0, {%1, %2};" : "=l"(r) : "f"(lo), "f"(hi));
    return r;
}
__device__ __forceinline__ void unpack2(u64 v, float& lo, float& hi) {
    asm("mov.b64 {%0, %1}, %2;" : "=f"(lo), "=f"(hi) : "l"(v));
}

#define MBARRIER_INIT(addr, count) \
    asm volatile("mbarrier.init.shared.b64 [%0], %1;" \
                 :: "r"((uint32_t)(addr)), "r"((uint32_t)(count)) : "memory")

#define MBARRIER_EXPECT_TX(addr, bytes) \
    asm volatile("mbarrier.arrive.expect_tx.shared.b64 _, [%0], %1;" \
                 :: "r"((uint32_t)(addr)), "r"((uint32_t)(bytes)) : "memory")

#define MBARRIER_WAIT_PARITY(mbar_smem_addr, phase_parity) do { \
    uint32_t _mbar = (uint32_t)(mbar_smem_addr); \
    uint32_t _parity = (uint32_t)(phase_parity); \
    uint32_t _done; \
    asm volatile( \
        "{\n\t" \
        ".reg .pred p;\n\t" \
        "mbarrier.try_wait.parity.acquire.cta.shared::cta.b64 p, [%1], %2;\n\t" \
        "selp.b32 %0, 1, 0, p;\n\t" \
        "}" \
        : "=r"(_done) : "r"(_mbar), "r"(_parity) : "memory"); \
    if (!_done) { \
        asm volatile( \
            "{\n\t" \
            ".reg .pred P1;\n\t" \
            "WAIT_LOOP_%=:\n\t" \
            "mbarrier.try_wait.parity.acquire.cta.shared::cta.b64 P1, [%0], %1, 0x989680;\n\t" \
            "@P1 bra.uni WAIT_DONE_%=;\n\t" \
            "bra.uni WAIT_LOOP_%=;\n\t" \
            "WAIT_DONE_%=:\n\t" \
            "}" \
            :: "r"(_mbar), "r"(_parity) : "memory"); \
    } \
} while (0)

#define BULK_G2S(dst_smem, src_gmem, nbytes, mbar) \
    asm volatile("cp.async.bulk.shared::cluster.global.mbarrier::complete_tx::bytes " \
                 "[%0], [%1], %2, [%3];" \
                 :: "r"((uint32_t)(dst_smem)), "l"(src_gmem), \
                    "r"((uint32_t)(nbytes)), "r"((uint32_t)(mbar)) : "memory")

// ---------------- One kernel, two roles, 2 CTAs/SM ----------------
// blockIdx < 512: work CTA — stream 256 seq rows (1 MiB) through a 3-deep
//   pipeline of 32 KiB (8-row) stages. Warp w consumes row w of each stage.
//   Co-resident CTA on the same SM fills DRAM-demand gaps (barriers, epilogue).
// blockIdx >= 512: combine CTA for batch b — last wave; waits for 8 splits,
//   merges from L2, writes output.
__global__ void __launch_bounds__(256, 2)
attn_kernel(const float* __restrict__ enc, const float* __restrict__ hn,
            float* __restrict__ out)
{
    const int tid = threadIdx.x;

    // ================= Combine role =================
    if (blockIdx.x >= WORK_CTAS) {
        const int b = blockIdx.x - WORK_CTAS;
        __shared__ int ready;
        if (tid == 0) {
            while (atomicAdd(&g_cnt[b], 0) != NSPLIT) __nanosleep(200);
            g_cnt[b] = 0;                 // self-reset for next graph replay
            ready = 1;
        }
        __syncthreads();
        (void)ready;
        __threadfence();                  // acquire partials

        float ml_m[NSPLIT], ml_l[NSPLIT];
#pragma unroll
        for (int s2 = 0; s2 < NSPLIT; s2++) {
            ml_m[s2] = g_ml[(b * NSPLIT + s2) * 2 + 0];
            ml_l[s2] = g_ml[(b * NSPLIT + s2) * 2 + 1];
        }
        float GM = ml_m[0];
#pragma unroll
        for (int s2 = 1; s2 < NSPLIT; s2++) GM = fmaxf(GM, ml_m[s2]);
        float GL = 0.f;
#pragma unroll
        for (int s2 = 0; s2 < NSPLIT; s2++) GL += ml_l[s2] * __expf(ml_m[s2] - GM);

        float4 a = make_float4(0.f, 0.f, 0.f, 0.f);
        const float4* num4 = (const float4*)g_num;
#pragma unroll
        for (int s2 = 0; s2 < NSPLIT; s2++) {
            const float fs = __expf(ml_m[s2] - GM);
            const float4 t = num4[(size_t)(b * NSPLIT + s2) * 256 + tid];
            a.x += fs * t.x; a.y += fs * t.y; a.z += fs * t.z; a.w += fs * t.w;
        }
        const float inv = 1.0f / GL;

        float4* out4 = (float4*)out;
        out4[(size_t)b * 512 + tid] = ((const float4*)(hn + (size_t)b * H_DIM))[tid];
        float4 ctx;
        ctx.x = a.x * inv; ctx.y = a.y * inv; ctx.z = a.z * inv; ctx.w = a.w * inv;
        out4[(size_t)b * 512 + 256 + tid] = ctx;
        return;
    }

    // ================= Work role =================
    extern __shared__ char smem[];
    const int wid = tid >> 5;
    const int ln  = tid & 31;
    const int b   = blockIdx.x / NSPLIT;
    const int sp  = blockIdx.x % NSPLIT;

    const char* src_base =
        (const char*)(enc + ((size_t)b * SEQ + (size_t)sp * ROWS_PER_CTA) * H_DIM);

    const uint32_t sbase = smem_u32(smem);
    const uint32_t mbar0 = sbase + SMEM_BUF_BYTES;
    float* msh = (float*)(smem + SMEM_BUF_BYTES + 32);
    float* lsh = msh + 8;

    if (tid == 0) {
#pragma unroll
        for (int s = 0; s < NBUF; s++) MBARRIER_INIT(mbar0 + 8 * s, 1);
    }
    __syncthreads();

    // h_n[b] as packed f32x2 pairs matching the per-lane column map
    const ulonglong2* h2 = (const ulonglong2*)(hn + (size_t)b * H_DIM);
    ulonglong2 hreg[8];
#pragma unroll
    for (int i = 0; i < 8; i++) hreg[i] = h2[i * 32 + ln];

    float m = -CUDART_INF_F;
    float l = 0.f;
    u64 acc[16];
#pragma unroll
    for (int i = 0; i < 16; i++) acc[i] = 0ull;

    // Prologue: fill the pipeline
    if (tid == 0) {
#pragma unroll
        for (int s = 0; s < NBUF; s++) {
            MBARRIER_EXPECT_TX(mbar0 + 8 * s, STAGE_BYTES);
            BULK_G2S(sbase + s * STAGE_BYTES,
                     src_base + (size_t)s * STAGE_BYTES,
                     STAGE_BYTES, mbar0 + 8 * s);
        }
    }

    for (int st = 0; st < NSTAGES; st++) {
        const int bsel = st % NBUF;
        const int par  = (st / NBUF) & 1;
        MBARRIER_WAIT_PARITY(mbar0 + 8 * bsel, par);

        // Warp wid consumes row wid of this 8-row stage
        {
            const ulonglong2* row = (const ulonglong2*)
                (smem + (size_t)bsel * STAGE_BYTES + (size_t)wid * (H_DIM * 4));
            ulonglong2 v[8];
#pragma unroll
            for (int i = 0; i < 8; i++) v[i] = row[i * 32 + ln];   // 16B lane stride: conflict-free

            // Packed dot: 16 fma2, 2 independent chains
            u64 p0 = 0ull, p1 = 0ull;
#pragma unroll
            for (int i = 0; i < 8; i++) {
                p0 = fma2(v[i].x, hreg[i].x, p0);
                p1 = fma2(v[i].y, hreg[i].y, p1);
            }
            float dl, dh;
            unpack2(add2(p0, p1), dl, dh);
            float d = dl + dh;
#pragma unroll
            for (int off = 16; off; off >>= 1)
                d += __shfl_xor_sync(0xffffffffu, d, off);

            // Warp-uniform branch: d identical across lanes
            if (d > m) {
                const float cf = __expf(m - d);    // exp(-inf)=0 on first row
                m = d;
                l = l * cf + 1.f;
                const u64 cf2 = pack2(cf, cf);
#pragma unroll
                for (int i = 0; i < 8; i++) {
                    acc[2 * i]     = fma2(acc[2 * i],     cf2, v[i].x);
                    acc[2 * i + 1] = fma2(acc[2 * i + 1], cf2, v[i].y);
                }
            } else {
                const float w = __expf(d - m);
                l += w;
                const u64 w2 = pack2(w, w);
#pragma unroll
                for (int i = 0; i < 8; i++) {
                    acc[2 * i]     = fma2(v[i].x, w2, acc[2 * i]);
                    acc[2 * i + 1] = fma2(v[i].y, w2, acc[2 * i + 1]);
                }
            }
        }
        __syncthreads();   // all warps done with buffer bsel
        if (tid == 0 && st + NBUF < NSTAGES) {
            MBARRIER_EXPECT_TX(mbar0 + 8 * bsel, STAGE_BYTES);
            BULK_G2S(sbase + bsel * STAGE_BYTES,
                     src_base + (size_t)(st + NBUF) * STAGE_BYTES,
                     STAGE_BYTES, mbar0 + 8 * bsel);
        }
    }

    // ---- Combine 8 warp partials within the CTA, write split partials ----
    if (ln == 0) { msh[wid] = m; lsh[wid] = l; }
    __syncthreads();

    float M = msh[0];
#pragma unroll
    for (int w2i = 1; w2i < 8; w2i++) M = fmaxf(M, msh[w2i]);
    float L = 0.f;
#pragma unroll
    for (int w2i = 0; w2i < 8; w2i++) L += lsh[w2i] * __expf(msh[w2i] - M);
    const float f = __expf(m - M);

    // Reuse stage buffers as [8 warps][256 float4] combine scratch (32 KiB)
    // (no TMA in flight: issues stopped at st+NBUF >= NSTAGES)
    float4* comb = (float4*)smem;
#pragma unroll
    for (int i = 0; i < 8; i++) {
        float ax, ay, az, aw;
        unpack2(acc[2 * i],     ax, ay);
        unpack2(acc[2 * i + 1], az, aw);
        float4 t;
        t.x = ax * f; t.y = ay * f; t.z = az * f; t.w = aw * f;
        comb[wid * 256 + i * 32 + ln] = t;
    }
    __syncthreads();

    float4 s = comb[tid];
#pragma unroll
    for (int w2i = 1; w2i < 8; w2i++) {
        const float4 t = comb[w2i * 256 + tid];
        s.x += t.x; s.y += t.y; s.z += t.z; s.w += t.w;
    }
    ((float4*)g_num)[(size_t)(b * NSPLIT + sp) * 256 + tid] = s;
    if (tid == 0) {
        g_ml[(b * NSPLIT + sp) * 2 + 0] = M;
        g_ml[(b * NSPLIT + sp) * 2 + 1] = L;
        __threadfence();                      // release partials
        atomicAdd(&g_cnt[b], 1);              // signal combine CTA
    }
}

// ---------------- Launch ----------------
extern "C" void kernel_launch(void* const* d_in, const int* in_sizes, int n_in,
                              void* d_out, int out_size)
{
    const float* enc = (const float*)d_in[0];   // (64, 2048, 1024) f32
    const float* hn  = (const float*)d_in[1];   // (64, 1024) f32
    float* out = (float*)d_out;                 // (64, 1, 2048) f32

    cudaFuncSetAttribute(attn_kernel,
                         cudaFuncAttributeMaxDynamicSharedMemorySize, SMEM_TOTAL);

    attn_kernel<<<GRID, 256, SMEM_TOTAL>>>(enc, hn, out);
}